// round 6
// baseline (speedup 1.0000x reference)
#include <cuda_runtime.h>

#define EPSF 1e-10f

// ---------------- scratch (device globals; no allocation) ----------------
// gathered points, row-major (N, c) per (level, batch)
__device__ __align__(128) float g_X[7778304];
__device__ __align__(128) float g_Y[7778304];
__device__ float    g_nx[32192];     // ||x_i|| per (l,b,n)
__device__ float    g_ny[32192];
__device__ unsigned g_rmax[32768];   // per (l,b): row max cos-sim (ordered-uint), stride 1024
__device__ unsigned g_cmax[32768];
__device__ float    g_mux[7680];     // per (l,b,ch)
__device__ float    g_muy[7680];
__device__ float    g_mud[32];       // mean |mu_x - mu_y| per (l,b)
__device__ float    g_style[32];
__device__ float    g_covpart[400];  // per b: 50 tile-partials (1+3+10+36)

// ordered-uint encoding of float (monotone), so atomicMax works on floats
__device__ __forceinline__ unsigned f2o(float f) {
    unsigned u = __float_as_uint(f);
    return (u & 0x80000000u) ? ~u : (u | 0x80000000u);
}
__device__ __forceinline__ float o2f(unsigned u) {
    return (u & 0x80000000u) ? __uint_as_float(u & 0x7FFFFFFFu)
                             : __uint_as_float(~u);
}

// ---------------- init: zero the atomicMax accumulators ----------------
__global__ void init_k() {
    int i = blockIdx.x * blockDim.x + threadIdx.x;
    if (i < 32768) { g_rmax[i] = 0u; g_cmax[i] = 0u; }
}

// ---------------- gather + per-point norms ----------------
// one block per (b, n); threads over channels
__global__ void gather_k(const float* __restrict__ tf, const float* __restrict__ gf,
                         const int* __restrict__ idx, int C, int HW, int N,
                         long xoff, int noff) {
    int b = blockIdx.x / N;
    int n = blockIdx.x - b * N;
    int p = idx ? idx[b * 1000 + n] : n;

    const float* tb = tf + (size_t)b * C * HW + p;
    const float* gb = gf + (size_t)b * C * HW + p;
    float* xr = g_X + xoff + ((size_t)b * N + n) * C;
    float* yr = g_Y + xoff + ((size_t)b * N + n) * C;

    float sx = 0.f, sy = 0.f;
    for (int ch = threadIdx.x; ch < C; ch += blockDim.x) {
        float vx = tb[(size_t)ch * HW];
        float vy = gb[(size_t)ch * HW];
        xr[ch] = vx; yr[ch] = vy;
        sx += vx * vx; sy += vy * vy;
    }
    __shared__ float buf[128];
    buf[threadIdx.x] = sx; __syncthreads();
    for (int s = 64; s > 0; s >>= 1) {
        if (threadIdx.x < s) buf[threadIdx.x] += buf[threadIdx.x + s];
        __syncthreads();
    }
    float tsx = buf[0]; __syncthreads();
    buf[threadIdx.x] = sy; __syncthreads();
    for (int s = 64; s > 0; s >>= 1) {
        if (threadIdx.x < s) buf[threadIdx.x] += buf[threadIdx.x + s];
        __syncthreads();
    }
    if (threadIdx.x == 0) {
        g_nx[noff + b * N + n] = sqrtf(tsx);
        g_ny[noff + b * N + n] = sqrtf(buf[0]);
    }
}

// ---------------- per-channel means + mu_d ----------------
// one block per batch (launched per level); deterministic per-thread column sums
__global__ void means_k(int C, int N, long xoff, int moff, int lb0) {
    int b = blockIdx.x;
    const float* X = g_X + xoff + (size_t)b * N * C;
    const float* Y = g_Y + xoff + (size_t)b * N * C;
    float local = 0.f;
    for (int ch = threadIdx.x; ch < C; ch += blockDim.x) {
        float sx = 0.f, sy = 0.f;
        const float* px = X + ch;
        const float* py = Y + ch;
        for (int n = 0; n < N; n++) { sx += *px; sy += *py; px += C; py += C; }
        float mx = sx / (float)N, my = sy / (float)N;
        g_mux[moff + b * C + ch] = mx;
        g_muy[moff + b * C + ch] = my;
        local += fabsf(mx - my);
    }
    __shared__ float buf[256];
    buf[threadIdx.x] = local; __syncthreads();
    for (int s = 128; s > 0; s >>= 1) {
        if (threadIdx.x < s) buf[threadIdx.x] += buf[threadIdx.x + s];
        __syncthreads();
    }
    if (threadIdx.x == 0) g_mud[lb0 + b] = buf[0] / (float)C;
}

// ---------------- cosine-similarity GEMM with fused row/col max ----------------
// 64x64 output tile, 256 threads, 4x4 per thread, k-chunks of 16
__global__ __launch_bounds__(256) void cos_k(int C, int N, long xoff, int noff, int lb0) {
    int b  = blockIdx.z;
    int i0 = blockIdx.y << 6;
    int j0 = blockIdx.x << 6;
    const float* X = g_X + xoff + (size_t)b * N * C;
    const float* Y = g_Y + xoff + (size_t)b * N * C;

    __shared__ __align__(16) float As[16][68];
    __shared__ __align__(16) float Bs[16][68];
    __shared__ unsigned srm[64], scm[64];

    int t  = threadIdx.x;
    if (t < 64) { srm[t] = 0u; scm[t] = 0u; }
    int li = t >> 2, lk = (t & 3) << 2;   // load: row 0..63, k 0,4,8,12
    int tx = t & 15, ty = t >> 4;          // compute 16x16 thread grid

    float acc[4][4] = {};

    for (int k0 = 0; k0 < C; k0 += 16) {
        float4 av = make_float4(0.f, 0.f, 0.f, 0.f);
        float4 bv = av;
        if (i0 + li < N) av = *(const float4*)&X[(size_t)(i0 + li) * C + k0 + lk];
        if (j0 + li < N) bv = *(const float4*)&Y[(size_t)(j0 + li) * C + k0 + lk];
        __syncthreads();
        As[lk + 0][li] = av.x; As[lk + 1][li] = av.y; As[lk + 2][li] = av.z; As[lk + 3][li] = av.w;
        Bs[lk + 0][li] = bv.x; Bs[lk + 1][li] = bv.y; Bs[lk + 2][li] = bv.z; Bs[lk + 3][li] = bv.w;
        __syncthreads();
#pragma unroll
        for (int k = 0; k < 16; k++) {
            float4 a  = *(const float4*)&As[k][ty << 2];
            float4 bb = *(const float4*)&Bs[k][tx << 2];
            float a4[4] = {a.x, a.y, a.z, a.w};
            float b4[4] = {bb.x, bb.y, bb.z, bb.w};
#pragma unroll
            for (int r = 0; r < 4; r++)
#pragma unroll
                for (int c = 0; c < 4; c++)
                    acc[r][c] += a4[r] * b4[c];
        }
    }

    // epilogue: normalize -> track maxima
    float rinv[4], cinv[4];
    bool  rv[4],  cv[4];
#pragma unroll
    for (int r = 0; r < 4; r++) {
        int i = i0 + (ty << 2) + r;
        rv[r] = (i < N);
        rinv[r] = rv[r] ? 1.f / (g_nx[noff + b * N + i] + EPSF) : 0.f;
    }
#pragma unroll
    for (int c = 0; c < 4; c++) {
        int j = j0 + (tx << 2) + c;
        cv[c] = (j < N);
        cinv[c] = cv[c] ? 1.f / (g_ny[noff + b * N + j] + EPSF) : 0.f;
    }
    float rp[4] = {-1e30f, -1e30f, -1e30f, -1e30f};
    float cp[4] = {-1e30f, -1e30f, -1e30f, -1e30f};
#pragma unroll
    for (int r = 0; r < 4; r++)
#pragma unroll
        for (int c = 0; c < 4; c++)
            if (rv[r] && cv[c]) {
                float s = acc[r][c] * rinv[r] * cinv[c];
                rp[r] = fmaxf(rp[r], s);
                cp[c] = fmaxf(cp[c], s);
            }
#pragma unroll
    for (int r = 0; r < 4; r++) if (rv[r]) atomicMax(&srm[(ty << 2) + r], f2o(rp[r]));
#pragma unroll
    for (int c = 0; c < 4; c++) if (cv[c]) atomicMax(&scm[(tx << 2) + c], f2o(cp[c]));
    __syncthreads();
    if (t < 64) {
        int lb = lb0 + b;
        if (i0 + t < N) atomicMax(&g_rmax[(lb << 10) + i0 + t], srm[t]);
        if (j0 + t < N) atomicMax(&g_cmax[(lb << 10) + j0 + t], scm[t]);
    }
}

// ---------------- covariance Gram tiles (upper-triangular only) ----------------
__global__ __launch_bounds__(256) void cov_k(int C, int N, long xoff, int moff, int covbase) {
    int b    = blockIdx.y;
    int nt   = C >> 6;
    int pair = blockIdx.x;
    int ti = 0, rem = pair;
    while (rem >= nt - ti) { rem -= nt - ti; ti++; }
    int tj = ti + rem;

    const float* X = g_X + xoff + (size_t)b * N * C;
    const float* Y = g_Y + xoff + (size_t)b * N * C;

    __shared__ __align__(16) float Axi[16][68];
    __shared__ __align__(16) float Axj[16][68];
    __shared__ __align__(16) float Ayi[16][68];
    __shared__ __align__(16) float Ayj[16][68];

    int t  = threadIdx.x;
    int lr = t >> 4;           // k row 0..15
    int lc = (t & 15) << 2;    // col 0..60
    int tx = t & 15, ty = t >> 4;
    int ci0 = ti << 6, cj0 = tj << 6;

    float gx[4][4] = {}, gy[4][4] = {};

    for (int k0 = 0; k0 < N; k0 += 16) {
        int kk = k0 + lr;
        float4 xi = make_float4(0.f, 0.f, 0.f, 0.f);
        float4 xj = xi, yi = xi, yj = xi;
        if (kk < N) {
            xi = *(const float4*)&X[(size_t)kk * C + ci0 + lc];
            xj = *(const float4*)&X[(size_t)kk * C + cj0 + lc];
            yi = *(const float4*)&Y[(size_t)kk * C + ci0 + lc];
            yj = *(const float4*)&Y[(size_t)kk * C + cj0 + lc];
        }
        __syncthreads();
        *(float4*)&Axi[lr][lc] = xi;
        *(float4*)&Axj[lr][lc] = xj;
        *(float4*)&Ayi[lr][lc] = yi;
        *(float4*)&Ayj[lr][lc] = yj;
        __syncthreads();
#pragma unroll
        for (int k = 0; k < 16; k++) {
            float4 ax = *(const float4*)&Axi[k][ty << 2];
            float4 bx = *(const float4*)&Axj[k][tx << 2];
            float4 ay = *(const float4*)&Ayi[k][ty << 2];
            float4 by = *(const float4*)&Ayj[k][tx << 2];
            float axr[4] = {ax.x, ax.y, ax.z, ax.w};
            float bxr[4] = {bx.x, bx.y, bx.z, bx.w};
            float ayr[4] = {ay.x, ay.y, ay.z, ay.w};
            float byr[4] = {by.x, by.y, by.z, by.w};
#pragma unroll
            for (int r = 0; r < 4; r++)
#pragma unroll
                for (int c = 0; c < 4; c++) {
                    gx[r][c] += axr[r] * bxr[c];
                    gy[r][c] += ayr[r] * byr[c];
                }
        }
    }

    float Nf  = (float)N;
    float inv = 1.f / (Nf - 1.f);
    float mxi[4], myi[4], mxj[4], myj[4];
#pragma unroll
    for (int r = 0; r < 4; r++) {
        int ci = ci0 + (ty << 2) + r;
        mxi[r] = g_mux[moff + b * C + ci];
        myi[r] = g_muy[moff + b * C + ci];
    }
#pragma unroll
    for (int c = 0; c < 4; c++) {
        int cj = cj0 + (tx << 2) + c;
        mxj[c] = g_mux[moff + b * C + cj];
        myj[c] = g_muy[moff + b * C + cj];
    }
    float sum = 0.f;
#pragma unroll
    for (int r = 0; r < 4; r++)
#pragma unroll
        for (int c = 0; c < 4; c++) {
            int ci = ci0 + (ty << 2) + r;
            int cj = cj0 + (tx << 2) + c;
            float d = (gx[r][c] - Nf * mxi[r] * mxj[c]) - (gy[r][c] - Nf * myi[r] * myj[c]);
            float w = (ti < tj) ? 2.f : (ci < cj ? 2.f : (ci == cj ? 1.f : 0.f));
            sum += w * fabsf(d);
        }
    sum *= inv;

    __syncthreads();
    float* buf = &Axi[0][0];
    buf[t] = sum; __syncthreads();
    for (int s = 128; s > 0; s >>= 1) {
        if (t < s) buf[t] += buf[t + s];
        __syncthreads();
    }
    if (t == 0) g_covpart[b * 50 + covbase + pair] = buf[0];
}

// ---------------- style reduce: m1/m2 from row/col maxima ----------------
__global__ void style_k() {
    int lb = blockIdx.x;
    int l  = lb >> 3;
    int N  = (l == 3) ? 1024 : 1000;
    float s1 = 0.f, s2 = 0.f;
    for (int i = threadIdx.x; i < N; i += blockDim.x) {
        s1 += o2f(g_rmax[(lb << 10) + i]);
        s2 += o2f(g_cmax[(lb << 10) + i]);
    }
    __shared__ float buf[256];
    buf[threadIdx.x] = s1; __syncthreads();
    for (int s = 128; s > 0; s >>= 1) {
        if (threadIdx.x < s) buf[threadIdx.x] += buf[threadIdx.x + s];
        __syncthreads();
    }
    float t1 = buf[0]; __syncthreads();
    buf[threadIdx.x] = s2; __syncthreads();
    for (int s = 128; s > 0; s >>= 1) {
        if (threadIdx.x < s) buf[threadIdx.x] += buf[threadIdx.x + s];
        __syncthreads();
    }
    if (threadIdx.x == 0) {
        float m1 = 1.f - t1 / (float)N;
        float m2 = 1.f - buf[0] / (float)N;
        g_style[lb] = fmaxf(m1, m2);
    }
}

// ---------------- finalize ----------------
__global__ void final_k(float* out, int out_size) {
    if (threadIdx.x == 0 && blockIdx.x == 0) {
        const int Cc[4] = {64, 128, 256, 512};
        const int PB[4] = {0, 1, 4, 14};
        const int NP[4] = {1, 3, 10, 36};
        float total = 0.f;
        for (int l = 0; l < 4; l++) {
            float cc2 = (float)Cc[l] * (float)Cc[l];
            for (int b = 0; b < 8; b++) {
                float cov = 0.f;
                for (int p = 0; p < NP[l]; p++) cov += g_covpart[b * 50 + PB[l] + p];
                total += g_style[l * 8 + b] + g_mud[l * 8 + b] + cov / cc2;
            }
        }
        total *= 0.125f;
        for (int i = 0; i < out_size; i++) out[i] = total;
    }
}

// ---------------- launch ----------------
extern "C" void kernel_launch(void* const* d_in, const int* in_sizes, int n_in,
                              void* d_out, int out_size) {
    // Identify inputs by element count (robust to metadata ordering):
    // per feature-size, first occurrence = target, second = gen; idx in order.
    const float* tf[4] = {0, 0, 0, 0};
    const float* gf[4] = {0, 0, 0, 0};
    const int*   idx[3] = {0, 0, 0};
    int seen[4] = {0, 0, 0, 0};
    int ni = 0;
    const int FE[4] = {33554432, 16777216, 8388608, 4194304};
    for (int i = 0; i < n_in; i++) {
        int sz = in_sizes[i];
        if (sz == 8000) { if (ni < 3) idx[ni++] = (const int*)d_in[i]; continue; }
        for (int l = 0; l < 4; l++) {
            if (sz == FE[l]) {
                if (seen[l] == 0) tf[l] = (const float*)d_in[i];
                else              gf[l] = (const float*)d_in[i];
                seen[l]++;
                break;
            }
        }
    }

    static const int  C_[4]  = {64, 128, 256, 512};
    static const int  HW_[4] = {65536, 16384, 4096, 1024};
    static const int  N_[4]  = {1000, 1000, 1000, 1024};
    static const long XO_[4] = {0, 512000, 1536000, 3584000};
    static const int  NO_[4] = {0, 8000, 16000, 24000};
    static const int  MO_[4] = {0, 512, 1536, 3584};
    static const int  NP_[4] = {1, 3, 10, 36};
    static const int  PB_[4] = {0, 1, 4, 14};

    init_k<<<128, 256>>>();

    for (int l = 0; l < 4; l++)
        gather_k<<<8 * N_[l], 128>>>(tf[l], gf[l], (l < 3) ? idx[l] : (const int*)0,
                                     C_[l], HW_[l], N_[l], XO_[l], NO_[l]);

    for (int l = 0; l < 4; l++)
        means_k<<<8, 256>>>(C_[l], N_[l], XO_[l], MO_[l], l * 8);

    for (int l = 0; l < 4; l++) {
        dim3 g((N_[l] + 63) / 64, (N_[l] + 63) / 64, 8);
        cos_k<<<g, 256>>>(C_[l], N_[l], XO_[l], NO_[l], l * 8);
    }

    for (int l = 0; l < 4; l++) {
        dim3 g(NP_[l], 8);
        cov_k<<<g, 256>>>(C_[l], N_[l], XO_[l], MO_[l], PB_[l]);
    }

    style_k<<<32, 256>>>();
    final_k<<<1, 32>>>((float*)d_out, out_size);
}

// round 11
// speedup vs baseline: 1.0289x; 1.0289x over previous
#include <cuda_runtime.h>

#define EPSF 1e-10f

// ---------------- scratch (device globals; no allocation) ----------------
// gathered points, row-major (N, c) per (level, batch)
__device__ __align__(128) float g_X[7778304];
__device__ __align__(128) float g_Y[7778304];
__device__ float    g_nx[32192];     // ||x_i|| per (l,b,n)
__device__ float    g_ny[32192];
__device__ unsigned g_rmax[32768];   // per (l,b): row max cos-sim (ordered-uint), stride 1024
__device__ unsigned g_cmax[32768];
__device__ float    g_mux[7680];     // per (l,b,ch)
__device__ float    g_muy[7680];
__device__ float    g_mud[32];       // mean |mu_x - mu_y| per (l,b)
__device__ float    g_style[32];
__device__ float    g_covpart[400];  // per b: 50 tile-partials (1+3+10+36)

// ordered-uint encoding of float (monotone), so atomicMax works on floats
__device__ __forceinline__ unsigned f2o(float f) {
    unsigned u = __float_as_uint(f);
    return (u & 0x80000000u) ? ~u : (u | 0x80000000u);
}
__device__ __forceinline__ float o2f(unsigned u) {
    return (u & 0x80000000u) ? __uint_as_float(u & 0x7FFFFFFFu)
                             : __uint_as_float(~u);
}

// ---------------- init: zero the atomicMax accumulators ----------------
__global__ void init_k() {
    int i = blockIdx.x * blockDim.x + threadIdx.x;
    if (i < 32768) { g_rmax[i] = 0u; g_cmax[i] = 0u; }
}

// ---------------- gather + per-point norms ----------------
// one block per (b, n); threads over channels
__global__ void gather_k(const float* __restrict__ tf, const float* __restrict__ gf,
                         const int* __restrict__ idx, int C, int HW, int N,
                         long xoff, int noff) {
    int b = blockIdx.x / N;
    int n = blockIdx.x - b * N;
    int p = idx ? idx[b * 1000 + n] : n;

    const float* tb = tf + (size_t)b * C * HW + p;
    const float* gb = gf + (size_t)b * C * HW + p;
    float* xr = g_X + xoff + ((size_t)b * N + n) * C;
    float* yr = g_Y + xoff + ((size_t)b * N + n) * C;

    float sx = 0.f, sy = 0.f;
    for (int ch = threadIdx.x; ch < C; ch += blockDim.x) {
        float vx = tb[(size_t)ch * HW];
        float vy = gb[(size_t)ch * HW];
        xr[ch] = vx; yr[ch] = vy;
        sx += vx * vx; sy += vy * vy;
    }
    __shared__ float buf[128];
    buf[threadIdx.x] = sx; __syncthreads();
    for (int s = 64; s > 0; s >>= 1) {
        if (threadIdx.x < s) buf[threadIdx.x] += buf[threadIdx.x + s];
        __syncthreads();
    }
    float tsx = buf[0]; __syncthreads();
    buf[threadIdx.x] = sy; __syncthreads();
    for (int s = 64; s > 0; s >>= 1) {
        if (threadIdx.x < s) buf[threadIdx.x] += buf[threadIdx.x + s];
        __syncthreads();
    }
    if (threadIdx.x == 0) {
        g_nx[noff + b * N + n] = sqrtf(tsx);
        g_ny[noff + b * N + n] = sqrtf(buf[0]);
    }
}

// ---------------- per-channel means + mu_d ----------------
// one block per batch (launched per level); deterministic per-thread column sums
__global__ void means_k(int C, int N, long xoff, int moff, int lb0) {
    int b = blockIdx.x;
    const float* X = g_X + xoff + (size_t)b * N * C;
    const float* Y = g_Y + xoff + (size_t)b * N * C;
    float local = 0.f;
    for (int ch = threadIdx.x; ch < C; ch += blockDim.x) {
        float sx = 0.f, sy = 0.f;
        const float* px = X + ch;
        const float* py = Y + ch;
        for (int n = 0; n < N; n++) { sx += *px; sy += *py; px += C; py += C; }
        float mx = sx / (float)N, my = sy / (float)N;
        g_mux[moff + b * C + ch] = mx;
        g_muy[moff + b * C + ch] = my;
        local += fabsf(mx - my);
    }
    __shared__ float buf[256];
    buf[threadIdx.x] = local; __syncthreads();
    for (int s = 128; s > 0; s >>= 1) {
        if (threadIdx.x < s) buf[threadIdx.x] += buf[threadIdx.x + s];
        __syncthreads();
    }
    if (threadIdx.x == 0) g_mud[lb0 + b] = buf[0] / (float)C;
}

// ---------------- cosine-similarity GEMM with fused row/col max ----------------
// 64x64 output tile, 256 threads, 4x4 per thread, k-chunks of 16
__global__ __launch_bounds__(256) void cos_k(int C, int N, long xoff, int noff, int lb0) {
    int b  = blockIdx.z;
    int i0 = blockIdx.y << 6;
    int j0 = blockIdx.x << 6;
    const float* X = g_X + xoff + (size_t)b * N * C;
    const float* Y = g_Y + xoff + (size_t)b * N * C;

    __shared__ __align__(16) float As[16][68];
    __shared__ __align__(16) float Bs[16][68];
    __shared__ unsigned srm[64], scm[64];

    int t  = threadIdx.x;
    if (t < 64) { srm[t] = 0u; scm[t] = 0u; }
    int li = t >> 2, lk = (t & 3) << 2;   // load: row 0..63, k 0,4,8,12
    int tx = t & 15, ty = t >> 4;          // compute 16x16 thread grid

    float acc[4][4] = {};

    for (int k0 = 0; k0 < C; k0 += 16) {
        float4 av = make_float4(0.f, 0.f, 0.f, 0.f);
        float4 bv = av;
        if (i0 + li < N) av = *(const float4*)&X[(size_t)(i0 + li) * C + k0 + lk];
        if (j0 + li < N) bv = *(const float4*)&Y[(size_t)(j0 + li) * C + k0 + lk];
        __syncthreads();
        As[lk + 0][li] = av.x; As[lk + 1][li] = av.y; As[lk + 2][li] = av.z; As[lk + 3][li] = av.w;
        Bs[lk + 0][li] = bv.x; Bs[lk + 1][li] = bv.y; Bs[lk + 2][li] = bv.z; Bs[lk + 3][li] = bv.w;
        __syncthreads();
#pragma unroll
        for (int k = 0; k < 16; k++) {
            float4 a  = *(const float4*)&As[k][ty << 2];
            float4 bb = *(const float4*)&Bs[k][tx << 2];
            float a4[4] = {a.x, a.y, a.z, a.w};
            float b4[4] = {bb.x, bb.y, bb.z, bb.w};
#pragma unroll
            for (int r = 0; r < 4; r++)
#pragma unroll
                for (int c = 0; c < 4; c++)
                    acc[r][c] += a4[r] * b4[c];
        }
    }

    // epilogue: normalize -> track maxima
    float rinv[4], cinv[4];
    bool  rv[4],  cv[4];
#pragma unroll
    for (int r = 0; r < 4; r++) {
        int i = i0 + (ty << 2) + r;
        rv[r] = (i < N);
        rinv[r] = rv[r] ? 1.f / (g_nx[noff + b * N + i] + EPSF) : 0.f;
    }
#pragma unroll
    for (int c = 0; c < 4; c++) {
        int j = j0 + (tx << 2) + c;
        cv[c] = (j < N);
        cinv[c] = cv[c] ? 1.f / (g_ny[noff + b * N + j] + EPSF) : 0.f;
    }
    float rp[4] = {-1e30f, -1e30f, -1e30f, -1e30f};
    float cp[4] = {-1e30f, -1e30f, -1e30f, -1e30f};
#pragma unroll
    for (int r = 0; r < 4; r++)
#pragma unroll
        for (int c = 0; c < 4; c++)
            if (rv[r] && cv[c]) {
                float s = acc[r][c] * rinv[r] * cinv[c];
                rp[r] = fmaxf(rp[r], s);
                cp[c] = fmaxf(cp[c], s);
            }
#pragma unroll
    for (int r = 0; r < 4; r++) if (rv[r]) atomicMax(&srm[(ty << 2) + r], f2o(rp[r]));
#pragma unroll
    for (int c = 0; c < 4; c++) if (cv[c]) atomicMax(&scm[(tx << 2) + c], f2o(cp[c]));
    __syncthreads();
    if (t < 64) {
        int lb = lb0 + b;
        if (i0 + t < N) atomicMax(&g_rmax[(lb << 10) + i0 + t], srm[t]);
        if (j0 + t < N) atomicMax(&g_cmax[(lb << 10) + j0 + t], scm[t]);
    }
}

// ---------------- covariance Gram tiles (upper-triangular only) ----------------
__global__ __launch_bounds__(256) void cov_k(int C, int N, long xoff, int moff, int covbase) {
    int b    = blockIdx.y;
    int nt   = C >> 6;
    int pair = blockIdx.x;
    int ti = 0, rem = pair;
    while (rem >= nt - ti) { rem -= nt - ti; ti++; }
    int tj = ti + rem;

    const float* X = g_X + xoff + (size_t)b * N * C;
    const float* Y = g_Y + xoff + (size_t)b * N * C;

    __shared__ __align__(16) float Axi[16][68];
    __shared__ __align__(16) float Axj[16][68];
    __shared__ __align__(16) float Ayi[16][68];
    __shared__ __align__(16) float Ayj[16][68];

    int t  = threadIdx.x;
    int lr = t >> 4;           // k row 0..15
    int lc = (t & 15) << 2;    // col 0..60
    int tx = t & 15, ty = t >> 4;
    int ci0 = ti << 6, cj0 = tj << 6;

    float gx[4][4] = {}, gy[4][4] = {};

    for (int k0 = 0; k0 < N; k0 += 16) {
        int kk = k0 + lr;
        float4 xi = make_float4(0.f, 0.f, 0.f, 0.f);
        float4 xj = xi, yi = xi, yj = xi;
        if (kk < N) {
            xi = *(const float4*)&X[(size_t)kk * C + ci0 + lc];
            xj = *(const float4*)&X[(size_t)kk * C + cj0 + lc];
            yi = *(const float4*)&Y[(size_t)kk * C + ci0 + lc];
            yj = *(const float4*)&Y[(size_t)kk * C + cj0 + lc];
        }
        __syncthreads();
        *(float4*)&Axi[lr][lc] = xi;
        *(float4*)&Axj[lr][lc] = xj;
        *(float4*)&Ayi[lr][lc] = yi;
        *(float4*)&Ayj[lr][lc] = yj;
        __syncthreads();
#pragma unroll
        for (int k = 0; k < 16; k++) {
            float4 ax = *(const float4*)&Axi[k][ty << 2];
            float4 bx = *(const float4*)&Axj[k][tx << 2];
            float4 ay = *(const float4*)&Ayi[k][ty << 2];
            float4 by = *(const float4*)&Ayj[k][tx << 2];
            float axr[4] = {ax.x, ax.y, ax.z, ax.w};
            float bxr[4] = {bx.x, bx.y, bx.z, bx.w};
            float ayr[4] = {ay.x, ay.y, ay.z, ay.w};
            float byr[4] = {by.x, by.y, by.z, by.w};
#pragma unroll
            for (int r = 0; r < 4; r++)
#pragma unroll
                for (int c = 0; c < 4; c++) {
                    gx[r][c] += axr[r] * bxr[c];
                    gy[r][c] += ayr[r] * byr[c];
                }
        }
    }

    float Nf  = (float)N;
    float inv = 1.f / (Nf - 1.f);
    float mxi[4], myi[4], mxj[4], myj[4];
#pragma unroll
    for (int r = 0; r < 4; r++) {
        int ci = ci0 + (ty << 2) + r;
        mxi[r] = g_mux[moff + b * C + ci];
        myi[r] = g_muy[moff + b * C + ci];
    }
#pragma unroll
    for (int c = 0; c < 4; c++) {
        int cj = cj0 + (tx << 2) + c;
        mxj[c] = g_mux[moff + b * C + cj];
        myj[c] = g_muy[moff + b * C + cj];
    }
    float sum = 0.f;
#pragma unroll
    for (int r = 0; r < 4; r++)
#pragma unroll
        for (int c = 0; c < 4; c++) {
            int ci = ci0 + (ty << 2) + r;
            int cj = cj0 + (tx << 2) + c;
            float d = (gx[r][c] - Nf * mxi[r] * mxj[c]) - (gy[r][c] - Nf * myi[r] * myj[c]);
            float w = (ti < tj) ? 2.f : (ci < cj ? 2.f : (ci == cj ? 1.f : 0.f));
            sum += w * fabsf(d);
        }
    sum *= inv;

    __syncthreads();
    float* buf = &Axi[0][0];
    buf[t] = sum; __syncthreads();
    for (int s = 128; s > 0; s >>= 1) {
        if (t < s) buf[t] += buf[t + s];
        __syncthreads();
    }
    if (t == 0) g_covpart[b * 50 + covbase + pair] = buf[0];
}

// ---------------- style reduce: m1/m2 from row/col maxima ----------------
__global__ void style_k() {
    int lb = blockIdx.x;
    int l  = lb >> 3;
    int N  = (l == 3) ? 1024 : 1000;
    float s1 = 0.f, s2 = 0.f;
    for (int i = threadIdx.x; i < N; i += blockDim.x) {
        s1 += o2f(g_rmax[(lb << 10) + i]);
        s2 += o2f(g_cmax[(lb << 10) + i]);
    }
    __shared__ float buf[256];
    buf[threadIdx.x] = s1; __syncthreads();
    for (int s = 128; s > 0; s >>= 1) {
        if (threadIdx.x < s) buf[threadIdx.x] += buf[threadIdx.x + s];
        __syncthreads();
    }
    float t1 = buf[0]; __syncthreads();
    buf[threadIdx.x] = s2; __syncthreads();
    for (int s = 128; s > 0; s >>= 1) {
        if (threadIdx.x < s) buf[threadIdx.x] += buf[threadIdx.x + s];
        __syncthreads();
    }
    if (threadIdx.x == 0) {
        float m1 = 1.f - t1 / (float)N;
        float m2 = 1.f - buf[0] / (float)N;
        g_style[lb] = fmaxf(m1, m2);
    }
}

// ---------------- finalize ----------------
__global__ void final_k(float* out, int out_size) {
    if (threadIdx.x == 0 && blockIdx.x == 0) {
        const int Cc[4] = {64, 128, 256, 512};
        const int PB[4] = {0, 1, 4, 14};
        const int NP[4] = {1, 3, 10, 36};
        float total = 0.f;
        for (int l = 0; l < 4; l++) {
            float cc2 = (float)Cc[l] * (float)Cc[l];
            for (int b = 0; b < 8; b++) {
                float cov = 0.f;
                for (int p = 0; p < NP[l]; p++) cov += g_covpart[b * 50 + PB[l] + p];
                total += g_style[l * 8 + b] + g_mud[l * 8 + b] + cov / cc2;
            }
        }
        total *= 0.125f;
        for (int i = 0; i < out_size; i++) out[i] = total;
    }
}

// ---------------- launch ----------------
extern "C" void kernel_launch(void* const* d_in, const int* in_sizes, int n_in,
                              void* d_out, int out_size) {
    // Identify inputs by element count (robust to metadata ordering):
    // per feature-size, first occurrence = target, second = gen; idx in order.
    const float* tf[4] = {0, 0, 0, 0};
    const float* gf[4] = {0, 0, 0, 0};
    const int*   idx[3] = {0, 0, 0};
    int seen[4] = {0, 0, 0, 0};
    int ni = 0;
    const int FE[4] = {33554432, 16777216, 8388608, 4194304};
    for (int i = 0; i < n_in; i++) {
        int sz = in_sizes[i];
        if (sz == 8000) { if (ni < 3) idx[ni++] = (const int*)d_in[i]; continue; }
        for (int l = 0; l < 4; l++) {
            if (sz == FE[l]) {
                if (seen[l] == 0) tf[l] = (const float*)d_in[i];
                else              gf[l] = (const float*)d_in[i];
                seen[l]++;
                break;
            }
        }
    }

    static const int  C_[4]  = {64, 128, 256, 512};
    static const int  HW_[4] = {65536, 16384, 4096, 1024};
    static const int  N_[4]  = {1000, 1000, 1000, 1024};
    static const long XO_[4] = {0, 512000, 1536000, 3584000};
    static const int  NO_[4] = {0, 8000, 16000, 24000};
    static const int  MO_[4] = {0, 512, 1536, 3584};
    static const int  NP_[4] = {1, 3, 10, 36};
    static const int  PB_[4] = {0, 1, 4, 14};

    init_k<<<128, 256>>>();

    for (int l = 0; l < 4; l++)
        gather_k<<<8 * N_[l], 128>>>(tf[l], gf[l], (l < 3) ? idx[l] : (const int*)0,
                                     C_[l], HW_[l], N_[l], XO_[l], NO_[l]);

    for (int l = 0; l < 4; l++)
        means_k<<<8, 256>>>(C_[l], N_[l], XO_[l], MO_[l], l * 8);

    for (int l = 0; l < 4; l++) {
        dim3 g((N_[l] + 63) / 64, (N_[l] + 63) / 64, 8);
        cos_k<<<g, 256>>>(C_[l], N_[l], XO_[l], NO_[l], l * 8);
    }

    for (int l = 0; l < 4; l++) {
        dim3 g(NP_[l], 8);
        cov_k<<<g, 256>>>(C_[l], N_[l], XO_[l], MO_[l], PB_[l]);
    }

    style_k<<<32, 256>>>();
    final_k<<<1, 32>>>((float*)d_out, out_size);
}